// round 1
// baseline (speedup 1.0000x reference)
#include <cuda_runtime.h>

#define BB 16
#define HH 512
#define WW 512
#define NCH 16          // h-chunks per column scan
#define CHROWS 32       // HH / NCH
#define WTILE 32        // w-lanes per ys block

// scratch: column cumsum result y_s[b][h][w]
__device__ float g_ys[(size_t)BB * HH * WW];

__device__ __forceinline__ float dgf(float t) {
    // c=2: 2 / (1 + exp(-t))
    return 2.0f / (1.0f + __expf(-t));
}

// ---------------------------------------------------------------------------
// Kernel 1: y_s = cumsum over H of dg(defgrad[...,1]).
// Block: 512 threads = WTILE(32) w-lanes x NCH(16) chunks of CHROWS(32) rows.
// Phase A: per-thread chunk sum. Phase B: smem exclusive chunk prefix.
// Phase C: re-walk chunk, write running cumsum (coalesced stores).
// Grid: BB * (WW/WTILE) = 256 blocks.
// ---------------------------------------------------------------------------
__global__ void __launch_bounds__(512) ys_kernel(const float* __restrict__ defgrad) {
    __shared__ float csum[NCH][WTILE];
    __shared__ float coff[NCH][WTILE];

    const int tilesPerB = WW / WTILE;            // 16
    const int b  = blockIdx.x / tilesPerB;
    const int w0 = (blockIdx.x % tilesPerB) * WTILE;
    const int wl = threadIdx.x & (WTILE - 1);
    const int ch = threadIdx.x / WTILE;
    const int w  = w0 + wl;
    const int h0 = ch * CHROWS;

    const float* base = defgrad + ((size_t)b * HH * WW) * 2 + (size_t)w * 2 + 1;

    float s = 0.f;
    #pragma unroll 4
    for (int r = 0; r < CHROWS; r++) {
        s += dgf(__ldg(base + (size_t)(h0 + r) * (WW * 2)));
    }
    csum[ch][wl] = s;
    __syncthreads();

    if (threadIdx.x < WTILE) {
        float acc = 0.f;
        #pragma unroll
        for (int c = 0; c < NCH; c++) {
            float t = csum[c][threadIdx.x];
            coff[c][threadIdx.x] = acc;   // exclusive prefix
            acc += t;
        }
    }
    __syncthreads();

    float acc = coff[ch][wl];
    float* ys = g_ys + (size_t)b * HH * WW + w;
    #pragma unroll 4
    for (int r = 0; r < CHROWS; r++) {
        acc += dgf(__ldg(base + (size_t)(h0 + r) * (WW * 2)));
        ys[(size_t)(h0 + r) * WW] = acc;
    }
}

// ---------------------------------------------------------------------------
// Kernel 2: per-row fused: block scan of dg(defgrad[...,0]) -> x_s (registers),
// affine -> (x,y,z), write grid3, bilinear gather from im, write out.
// Grid: BB*HH = 8192 blocks of 512 threads (one thread per w).
// ---------------------------------------------------------------------------
__global__ void __launch_bounds__(512) main_kernel(
    const float*  __restrict__ im,
    const float*  __restrict__ defgrad,
    const float*  __restrict__ affine,
    float*        __restrict__ out,
    float*        __restrict__ grid3)
{
    const int b = blockIdx.x >> 9;     // / HH
    const int h = blockIdx.x & (HH - 1);
    const int w = threadIdx.x;
    const int lane = w & 31;
    const int warp = w >> 5;

    const size_t rowbase = ((size_t)b * HH + h) * WW;

    // dg for x-channel
    float v = dgf(__ldg(defgrad + (rowbase + w) * 2));

    // block-wide inclusive scan (512 threads)
    #pragma unroll
    for (int o = 1; o < 32; o <<= 1) {
        float n = __shfl_up_sync(0xffffffffu, v, o);
        if (lane >= o) v += n;
    }
    __shared__ float wsum[16];
    if (lane == 31) wsum[warp] = v;
    __syncthreads();
    if (threadIdx.x < 16) {
        float s = wsum[threadIdx.x];
        #pragma unroll
        for (int o = 1; o < 16; o <<= 1) {
            float n = __shfl_up_sync(0xffffu, s, o);
            if ((int)threadIdx.x >= o) s += n;
        }
        wsum[threadIdx.x] = s;
    }
    __syncthreads();
    const float xs = v + (warp ? wsum[warp - 1] : 0.f);

    const float ys = g_ys[rowbase + w];

    // residual affine (A = affine.reshape(3,3) + I); uniform per-block loads
    const float* A = affine + b * 9;
    const float a0 = __ldg(A + 0) + 1.f, a1 = __ldg(A + 1),       a2 = __ldg(A + 2);
    const float a3 = __ldg(A + 3),       a4 = __ldg(A + 4) + 1.f, a5 = __ldg(A + 5);
    const float a6 = __ldg(A + 6),       a7 = __ldg(A + 7),       a8 = __ldg(A + 8) + 1.f;

    const float x = a0 * xs + a1 * ys + a2;
    const float y = a3 * xs + a4 * ys + a5;
    const float z = a6 * xs + a7 * ys + a8;

    // grid3 output [B,H,W,3]
    const size_t gidx = (rowbase + w) * 3;
    grid3[gidx + 0] = x;
    grid3[gidx + 1] = y;
    grid3[gidx + 2] = z;

    // bilinear sample with clamped corner indices (matches reference exactly)
    const int fx = (int)floorf(x);
    const int fy = (int)floorf(y);
    const int x0 = min(max(fx,     0), WW - 1);
    const int x1 = min(max(fx + 1, 0), WW - 1);
    const int y0 = min(max(fy,     0), HH - 1);
    const int y1 = min(max(fy + 1, 0), HH - 1);

    const float x0f = (float)x0, x1f = (float)x1;
    const float y0f = (float)y0, y1f = (float)y1;

    const float wa = (x1f - x) * (y1f - y);
    const float wb = (x1f - x) * (y - y0f);
    const float wc = (x - x0f) * (y1f - y);
    const float wd = (x - x0f) * (y - y0f);

    const float4* imb = reinterpret_cast<const float4*>(im) + (size_t)b * HH * WW;
    const float4 Ia = __ldg(&imb[(size_t)y0 * WW + x0]);
    const float4 Ib = __ldg(&imb[(size_t)y1 * WW + x0]);
    const float4 Ic = __ldg(&imb[(size_t)y0 * WW + x1]);
    const float4 Id = __ldg(&imb[(size_t)y1 * WW + x1]);

    float4 o;
    o.x = wa * Ia.x + wb * Ib.x + wc * Ic.x + wd * Id.x;
    o.y = wa * Ia.y + wb * Ib.y + wc * Ic.y + wd * Id.y;
    o.z = wa * Ia.z + wb * Ib.z + wc * Ic.z + wd * Id.z;
    o.w = wa * Ia.w + wb * Ib.w + wc * Ic.w + wd * Id.w;

    reinterpret_cast<float4*>(out)[rowbase + w] = o;
}

// ---------------------------------------------------------------------------
extern "C" void kernel_launch(void* const* d_in, const int* in_sizes, int n_in,
                              void* d_out, int out_size) {
    const float* im      = (const float*)d_in[0];   // [16,512,512,4] f32
    const float* defgrad = (const float*)d_in[1];   // [16,512,512,2] f32
    const float* affine  = (const float*)d_in[2];   // [16,9] f32

    float* out   = (float*)d_out;
    float* grid3 = out + (size_t)in_sizes[0];       // im count == out count

    ys_kernel<<<BB * (WW / WTILE), 512>>>(defgrad);
    main_kernel<<<(unsigned)(BB * HH), 512>>>(im, defgrad, affine, out, grid3);
}

// round 3
// speedup vs baseline: 1.2420x; 1.2420x over previous
#include <cuda_runtime.h>

#define BB 16
#define HH 512
#define WW 512

// ys kernel geometry: 16 w-lanes x 32 chunks of 16 rows
#define WT 16
#define NCH 32
#define CHR 16   // HH / NCH

// scratch: column cumsum result y_s[b][h][w]
__device__ float g_ys[(size_t)BB * HH * WW];

__device__ __forceinline__ float dgf(float t) {
    return 2.0f / (1.0f + __expf(-t));   // c=2 logistic
}

// ---------------------------------------------------------------------------
// Kernel 1: y_s = cumsum over H of dg(defgrad[...,1]).
// Single global pass: dg values cached in smem for the rewrite phase.
// Block: 512 thr = WT(16) w-lanes x NCH(32) chunks of CHR(16) rows.
// Grid: BB * (WW/WT) = 512 blocks.
// ---------------------------------------------------------------------------
__global__ void __launch_bounds__(512) ys_kernel(const float2* __restrict__ defgrad2) {
    __shared__ float cache[NCH][CHR][WT + 1];  // +1 pad: conflict-free
    __shared__ float csum[NCH][WT];
    __shared__ float coff[NCH][WT];

    const int tilesPerB = WW / WT;             // 32
    const int b  = blockIdx.x / tilesPerB;
    const int w0 = (blockIdx.x % tilesPerB) * WT;
    const int wl = threadIdx.x & (WT - 1);
    const int ch = threadIdx.x / WT;
    const int w  = w0 + wl;
    const int h0 = ch * CHR;

    const float2* base = defgrad2 + (size_t)b * HH * WW + w;

    float s = 0.f;
    #pragma unroll 4
    for (int r = 0; r < CHR; r++) {
        float v = dgf(__ldg(&base[(size_t)(h0 + r) * WW]).y);
        cache[ch][r][wl] = v;
        s += v;
    }
    csum[ch][wl] = s;
    __syncthreads();

    if (threadIdx.x < WT) {
        float acc = 0.f;
        #pragma unroll
        for (int c = 0; c < NCH; c++) {
            float t = csum[c][threadIdx.x];
            coff[c][threadIdx.x] = acc;   // exclusive chunk prefix
            acc += t;
        }
    }
    __syncthreads();

    float acc = coff[ch][wl];
    float* ys = g_ys + (size_t)b * HH * WW + w;
    #pragma unroll 4
    for (int r = 0; r < CHR; r++) {
        acc += cache[ch][r][wl];
        ys[(size_t)(h0 + r) * WW] = acc;
    }
}

// ---------------------------------------------------------------------------
// Kernel 2: TWO rows per block. Per row: block scan of dg_x -> x_s (regs),
// affine, grid3 (smem-staged coalesced float4 stores), bilinear gather, out.
// 8 gathers in flight per thread; row h+1 gather lines hit row h's in L1.
// Grid: BB*HH/2 = 4096 blocks of 512 threads.
// ---------------------------------------------------------------------------
__global__ void __launch_bounds__(512, 2) main_kernel(
    const float4* __restrict__ im4,
    const float2* __restrict__ defgrad2,
    const float*  __restrict__ affine,
    float4*       __restrict__ out4,
    float*        __restrict__ grid3)
{
    const int b  = blockIdx.x >> 8;            // / (HH/2)
    const int hp = blockIdx.x & 255;
    const int h0 = hp * 2;
    const int w    = threadIdx.x;
    const int lane = w & 31;
    const int warp = w >> 5;

    const size_t row0 = ((size_t)b * HH + h0) * WW;   // row h0 base
    const size_t row1 = row0 + WW;

    // issue all independent loads up front
    const float2 dgA = __ldg(defgrad2 + row0 + w);
    const float2 dgB = __ldg(defgrad2 + row1 + w);
    const float  ys0 = g_ys[row0 + w];
    const float  ys1 = g_ys[row1 + w];

    const float* A = affine + b * 9;
    const float a0 = __ldg(A + 0) + 1.f, a1 = __ldg(A + 1),       a2 = __ldg(A + 2);
    const float a3 = __ldg(A + 3),       a4 = __ldg(A + 4) + 1.f, a5 = __ldg(A + 5);
    const float a6 = __ldg(A + 6),       a7 = __ldg(A + 7),       a8 = __ldg(A + 8) + 1.f;

    float v0 = dgf(dgA.x);
    float v1 = dgf(dgB.x);

    // dual block-wide inclusive scan (both rows in parallel -> ILP)
    #pragma unroll
    for (int o = 1; o < 32; o <<= 1) {
        float n0 = __shfl_up_sync(0xffffffffu, v0, o);
        float n1 = __shfl_up_sync(0xffffffffu, v1, o);
        if (lane >= o) { v0 += n0; v1 += n1; }
    }
    __shared__ float wsum[2][16];
    if (lane == 31) { wsum[0][warp] = v0; wsum[1][warp] = v1; }
    __syncthreads();
    if (threadIdx.x < 32) {
        const int g = threadIdx.x >> 4, i = threadIdx.x & 15;
        float s = wsum[g][i];
        #pragma unroll
        for (int o = 1; o < 16; o <<= 1) {
            float n = __shfl_up_sync(0xffffffffu, s, o, 16);
            if (i >= o) s += n;
        }
        wsum[g][i] = s;
    }
    __syncthreads();
    const float xs0 = v0 + (warp ? wsum[0][warp - 1] : 0.f);
    const float xs1 = v1 + (warp ? wsum[1][warp - 1] : 0.f);

    // affine
    const float x_0 = a0 * xs0 + a1 * ys0 + a2;
    const float y_0 = a3 * xs0 + a4 * ys0 + a5;
    const float z_0 = a6 * xs0 + a7 * ys0 + a8;
    const float x_1 = a0 * xs1 + a1 * ys1 + a2;
    const float y_1 = a3 * xs1 + a4 * ys1 + a5;
    const float z_1 = a6 * xs1 + a7 * ys1 + a8;

    // corner indices
    const int fx0 = (int)floorf(x_0), fy0 = (int)floorf(y_0);
    const int fx1 = (int)floorf(x_1), fy1 = (int)floorf(y_1);
    const int x00 = min(max(fx0,     0), WW - 1);
    const int x01 = min(max(fx0 + 1, 0), WW - 1);
    const int y00 = min(max(fy0,     0), HH - 1);
    const int y01 = min(max(fy0 + 1, 0), HH - 1);
    const int x10 = min(max(fx1,     0), WW - 1);
    const int x11 = min(max(fx1 + 1, 0), WW - 1);
    const int y10 = min(max(fy1,     0), HH - 1);
    const int y11 = min(max(fy1 + 1, 0), HH - 1);

    // issue all 8 gathers before the grid3 staging barrier (overlap)
    const float4* imb = im4 + (size_t)b * HH * WW;
    const float4 Ia0 = __ldg(&imb[(size_t)y00 * WW + x00]);
    const float4 Ib0 = __ldg(&imb[(size_t)y01 * WW + x00]);
    const float4 Ic0 = __ldg(&imb[(size_t)y00 * WW + x01]);
    const float4 Id0 = __ldg(&imb[(size_t)y01 * WW + x01]);
    const float4 Ia1 = __ldg(&imb[(size_t)y10 * WW + x10]);
    const float4 Ib1 = __ldg(&imb[(size_t)y11 * WW + x10]);
    const float4 Ic1 = __ldg(&imb[(size_t)y10 * WW + x11]);
    const float4 Id1 = __ldg(&imb[(size_t)y11 * WW + x11]);

    // stage grid3 in smem, write back as coalesced float4s.
    // total = 2 rows * 512 * 3 floats = 3072 floats = 768 float4 = 512 + 256
    __shared__ float g3[2 * WW * 3];            // 12 KB
    g3[w * 3 + 0]          = x_0;
    g3[w * 3 + 1]          = y_0;
    g3[w * 3 + 2]          = z_0;
    g3[WW * 3 + w * 3 + 0] = x_1;
    g3[WW * 3 + w * 3 + 1] = y_1;
    g3[WW * 3 + w * 3 + 2] = z_1;
    __syncthreads();
    {
        float4* dst = reinterpret_cast<float4*>(grid3 + row0 * 3);
        const float4* src = reinterpret_cast<const float4*>(g3);
        dst[threadIdx.x] = src[threadIdx.x];                      // 0..511
        if (threadIdx.x < 256)
            dst[threadIdx.x + 512] = src[threadIdx.x + 512];      // 512..767
    }

    // bilinear weights + combine (gathers have had the barrier to land)
    {
        const float wx1 = (float)x01 - x_0, wx0 = x_0 - (float)x00;
        const float wy1 = (float)y01 - y_0, wy0 = y_0 - (float)y00;
        const float wa = wx1 * wy1, wb = wx1 * wy0, wc = wx0 * wy1, wd = wx0 * wy0;
        float4 o;
        o.x = wa * Ia0.x + wb * Ib0.x + wc * Ic0.x + wd * Id0.x;
        o.y = wa * Ia0.y + wb * Ib0.y + wc * Ic0.y + wd * Id0.y;
        o.z = wa * Ia0.z + wb * Ib0.z + wc * Ic0.z + wd * Id0.z;
        o.w = wa * Ia0.w + wb * Ib0.w + wc * Ic0.w + wd * Id0.w;
        out4[row0 + w] = o;
    }
    {
        const float wx1 = (float)x11 - x_1, wx0 = x_1 - (float)x10;
        const float wy1 = (float)y11 - y_1, wy0 = y_1 - (float)y10;
        const float wa = wx1 * wy1, wb = wx1 * wy0, wc = wx0 * wy1, wd = wx0 * wy0;
        float4 o;
        o.x = wa * Ia1.x + wb * Ib1.x + wc * Ic1.x + wd * Id1.x;
        o.y = wa * Ia1.y + wb * Ib1.y + wc * Ic1.y + wd * Id1.y;
        o.z = wa * Ia1.z + wb * Ib1.z + wc * Ic1.z + wd * Id1.z;
        o.w = wa * Ia1.w + wb * Ib1.w + wc * Ic1.w + wd * Id1.w;
        out4[row1 + w] = o;
    }
}

// ---------------------------------------------------------------------------
extern "C" void kernel_launch(void* const* d_in, const int* in_sizes, int n_in,
                              void* d_out, int out_size) {
    const float4* im4      = (const float4*)d_in[0];   // [16,512,512,4] f32
    const float2* defgrad2 = (const float2*)d_in[1];   // [16,512,512,2] f32
    const float*  affine   = (const float*)d_in[2];    // [16,9] f32

    float* out   = (float*)d_out;
    float* grid3 = out + (size_t)in_sizes[0];          // out has im's element count

    ys_kernel<<<BB * (WW / WT), 512>>>(defgrad2);
    main_kernel<<<(unsigned)(BB * HH / 2), 512>>>(im4, defgrad2, affine,
                                                  (float4*)out, grid3);
}